// round 3
// baseline (speedup 1.0000x reference)
#include <cuda_runtime.h>
#include <cstdint>

#define BSZ  32
#define SEQL 64
#define HID  256

// scratch (no cudaMalloc allowed)
__device__ float g_context[BSZ * HID];

// ---------- helpers ----------
__device__ __forceinline__ uint32_t s2u(const void* p) {
    uint32_t a;
    asm("{ .reg .u64 t; cvta.to.shared.u64 t, %1; cvt.u32.u64 %0, t; }" : "=r"(a) : "l"(p));
    return a;
}
__device__ __forceinline__ void ffma2(unsigned long long& d, unsigned long long a, unsigned long long b) {
    asm("fma.rn.f32x2 %0, %1, %2, %3;" : "=l"(d) : "l"(a), "l"(b), "l"(d));
}
__device__ __forceinline__ unsigned long long pk2(float a, float b) {
    unsigned long long r;
    asm("mov.b64 %0, {%1, %2};" : "=l"(r) : "f"(a), "f"(b));
    return r;
}
__device__ __forceinline__ float2 upk2(unsigned long long v) {
    float2 f;
    asm("mov.b64 {%0, %1}, %2;" : "=f"(f.x), "=f"(f.y) : "l"(v));
    return f;
}
__device__ __forceinline__ float sigf(float x)      { return __fdividef(1.0f, 1.0f + __expf(-x)); }
__device__ __forceinline__ float tanh_fast(float x) { return 1.0f - __fdividef(2.0f, __expf(2.0f * x) + 1.0f); }

__device__ __forceinline__ void mbar_wait(uint32_t addr, uint32_t parity) {
    asm volatile(
        "{\n\t"
        ".reg .pred P;\n\t"
        "WAIT_%=: \n\t"
        "mbarrier.try_wait.parity.acquire.cluster.shared::cta.b64 P, [%0], %1;\n\t"
        "@!P bra WAIT_%=;\n\t"
        "}"
        :: "r"(addr), "r"(parity) : "memory");
}
__device__ __forceinline__ void mbar_init(uint32_t addr, uint32_t cnt) {
    asm volatile("mbarrier.init.shared.b64 [%0], %1;" :: "r"(addr), "r"(cnt) : "memory");
}
__device__ __forceinline__ void mbar_arrive_expect(uint32_t addr, uint32_t tx) {
    asm volatile("mbarrier.arrive.expect_tx.shared.b64 _, [%0], %1;" :: "r"(addr), "r"(tx) : "memory");
}
__device__ __forceinline__ void st_async_f32(uint32_t laddr, uint32_t lbar, float v, int rank) {
    uint32_t ra, rb;
    asm("mapa.shared::cluster.u32 %0, %1, %2;" : "=r"(ra) : "r"(laddr), "r"(rank));
    asm("mapa.shared::cluster.u32 %0, %1, %2;" : "=r"(rb) : "r"(lbar), "r"(rank));
    asm volatile("st.async.shared::cluster.mbarrier::complete_tx::bytes.f32 [%0], %1, [%2];"
                 :: "r"(ra), "f"(v), "r"(rb) : "memory");
}

// ============================================================================
// K1: context[b][h] = sum_s softmax_s(x[b]@Wa_x)[s,h] * x[b,s,h]
// grid 128 = (b:32) x (hchunk:4), 256 threads   (unchanged — passed R1)
// ============================================================================
__global__ void __launch_bounds__(256) k_context(const float* __restrict__ x,
                                                 const float* __restrict__ Wa) {
    __shared__ __align__(16) float xt[64][65];
    __shared__ __align__(16) float wt_sc[64][64];

    const int b   = blockIdx.x >> 2;
    const int hc  = blockIdx.x & 3;
    const int tid = threadIdx.x;
    const int h4  = tid & 15;
    const int s4  = tid >> 4;
    const float* xb = x + b * SEQL * HID;

    float acc[4][4];
#pragma unroll
    for (int i = 0; i < 4; i++)
#pragma unroll
        for (int j = 0; j < 4; j++) acc[i][j] = 0.0f;

    for (int kt = 0; kt < 4; ++kt) {
#pragma unroll
        for (int it = 0; it < 16; ++it) {
            int i = it * 256 + tid;
            int s = i >> 6, kk = i & 63;
            xt[kk][s] = xb[s * HID + kt * 64 + kk];
        }
#pragma unroll
        for (int it = 0; it < 16; ++it) {
            int i = it * 256 + tid;
            int kk = i >> 6, hl = i & 63;
            wt_sc[kk][hl] = Wa[(kt * 64 + kk) * HID + hc * 64 + hl];
        }
        __syncthreads();
#pragma unroll 4
        for (int kk = 0; kk < 64; ++kk) {
            float a0 = xt[kk][s4 * 4 + 0];
            float a1 = xt[kk][s4 * 4 + 1];
            float a2 = xt[kk][s4 * 4 + 2];
            float a3 = xt[kk][s4 * 4 + 3];
            float4 wv = *reinterpret_cast<const float4*>(&wt_sc[kk][h4 * 4]);
            acc[0][0] += a0 * wv.x; acc[0][1] += a0 * wv.y; acc[0][2] += a0 * wv.z; acc[0][3] += a0 * wv.w;
            acc[1][0] += a1 * wv.x; acc[1][1] += a1 * wv.y; acc[1][2] += a1 * wv.z; acc[1][3] += a1 * wv.w;
            acc[2][0] += a2 * wv.x; acc[2][1] += a2 * wv.y; acc[2][2] += a2 * wv.z; acc[2][3] += a2 * wv.w;
            acc[3][0] += a3 * wv.x; acc[3][1] += a3 * wv.y; acc[3][2] += a3 * wv.z; acc[3][3] += a3 * wv.w;
        }
        __syncthreads();
    }

#pragma unroll
    for (int i = 0; i < 4; ++i) {
        *reinterpret_cast<float4*>(&wt_sc[s4 * 4 + i][h4 * 4]) =
            make_float4(acc[i][0], acc[i][1], acc[i][2], acc[i][3]);
    }
    __syncthreads();

    if (tid < 64) {
        const int h = tid;
        float m = -3.4e38f;
#pragma unroll 8
        for (int s = 0; s < 64; ++s) m = fmaxf(m, wt_sc[s][h]);
        float Z = 0.0f, C = 0.0f;
#pragma unroll 8
        for (int s = 0; s < 64; ++s) {
            float e = __expf(wt_sc[s][h] - m);
            Z += e;
            C += e * xb[s * HID + hc * 64 + h];
        }
        g_context[b * HID + hc * 64 + h] = C / Z;
    }
}

// ============================================================================
// K3: LSTM recurrence. 16 clusters x 8 CTAs, 2 batches/cluster.
// CTA rank r owns h in [r*32, r*32+32).
// thread = (hl: tid>>4, cp: (tid>>3)&1, kq: tid&7)
//   owns gate cols {2cp, 2cp+1} for hl, k in [kq*32, kq*32+32), both batches.
// Per step: FFMA2 matvec -> shfl k-reduce -> STS gates -> 1 syncthreads ->
// warps 0,1 pointwise (ct reg-resident) -> st.async scatter to 8 CTAs ->
// mbarrier parity wait (no cluster barrier, no DSMEM sync).
// ============================================================================
__global__ void __cluster_dims__(8, 1, 1) __launch_bounds__(512, 1)
k_recur(const float* __restrict__ Wi, const float* __restrict__ Wh,
        const float* __restrict__ bias, const float* __restrict__ Wf,
        const float* __restrict__ bf, float* __restrict__ out) {
    __shared__ __align__(16) float htbuf[2][2][256];    // [buf][b2][256]
    __shared__ __align__(16) float ctx_s[2][256];
    __shared__ __align__(16) float gsm[2][4][32];       // [b2][gate][hl]
    __shared__ __align__(16) float wstage[64][129];
    __shared__ float red_s[16];
    __shared__ __align__(8) unsigned long long mbar[2];

    const int tid = threadIdx.x;
    uint32_t rnk;
    asm("mov.u32 %0, %%cluster_ctarank;" : "=r"(rnk));
    const int r     = (int)rnk;
    const int cbase = (blockIdx.x >> 3) * 2;
    const int hl = tid >> 4;
    const int cp = (tid >> 3) & 1;
    const int kq = tid & 7;
    const int colA = (2 * cp) * 256 + r * 32 + hl;
    const int colB = colA + 256;

    const uint32_t htb     = s2u(&htbuf[0][0][0]);
    const uint32_t mbarb   = s2u(&mbar[0]);

    // ---- init ----
    ((float*)htbuf)[tid] = 0.0f;   // zero buffer 0 (512 floats)
    { int b2 = tid >> 8, k = tid & 255;
      ctx_s[b2][k] = g_context[(cbase + b2) * HID + k]; }
    if (tid == 0) {
        mbar_init(mbarb, 1);
        mbar_init(mbarb + 8, 1);
        mbar_arrive_expect(mbarb, 2048);
        mbar_arrive_expect(mbarb + 8, 2048);
    }
    __syncthreads();

    // ---- gbase = bias + ctx @ Wi (distributed like the step matvec) ----
    float a00 = 0.f, a01 = 0.f, a10 = 0.f, a11 = 0.f;
#pragma unroll 8
    for (int k = kq * 32; k < kq * 32 + 32; ++k) {
        float w0 = __ldg(&Wi[k * 1024 + colA]);
        float w1 = __ldg(&Wi[k * 1024 + colB]);
        float c0 = ctx_s[0][k], c1 = ctx_s[1][k];
        a00 += c0 * w0; a01 += c0 * w1;
        a10 += c1 * w0; a11 += c1 * w1;
    }
#pragma unroll
    for (int off = 1; off < 8; off <<= 1) {
        a00 += __shfl_xor_sync(0xffffffffu, a00, off);
        a01 += __shfl_xor_sync(0xffffffffu, a01, off);
        a10 += __shfl_xor_sync(0xffffffffu, a10, off);
        a11 += __shfl_xor_sync(0xffffffffu, a11, off);
    }
    if (kq == 0) {
        gsm[0][2 * cp][hl]     = a00;
        gsm[0][2 * cp + 1][hl] = a01;
        gsm[1][2 * cp][hl]     = a10;
        gsm[1][2 * cp + 1][hl] = a11;
    }
    __syncthreads();

    float gb0 = 0.f, gb1 = 0.f, gb2 = 0.f, gb3 = 0.f, ct = 0.f;
    if (tid < 64) {
        int b2 = tid >> 5, l = tid & 31;
        gb0 = gsm[b2][0][l] + bias[0 * 256 + r * 32 + l];
        gb1 = gsm[b2][1][l] + bias[1 * 256 + r * 32 + l];
        gb2 = gsm[b2][2][l] + bias[2 * 256 + r * 32 + l];
        gb3 = gsm[b2][3][l] + bias[3 * 256 + r * 32 + l];
    }
    __syncthreads();   // protect gsm before loop reuses it

    // ---- stage Wh slice through smem (coalesced), pack into registers ----
    unsigned long long wA[16], wB[16];
    const int lcA = cp * 64 + hl;     // local col of gate 2cp
    const int lcB = lcA + 32;         // local col of gate 2cp+1
    const int my_kk  = kq >> 1;
    const int khalf  = kq & 1;
    for (int kk = 0; kk < 4; ++kk) {
#pragma unroll
        for (int it = 0; it < 16; ++it) {
            int i = it * 512 + tid;
            int kr = i >> 7, c = i & 127;
            int col = (c >> 5) * 256 + r * 32 + (c & 31);
            wstage[kr][c] = Wh[(kk * 64 + kr) * 1024 + col];
        }
        __syncthreads();
        if (kk == my_kk) {
#pragma unroll
            for (int p = 0; p < 16; ++p) {
                int kr = khalf * 32 + 2 * p;
                wA[p] = pk2(wstage[kr][lcA], wstage[kr + 1][lcA]);
                wB[p] = pk2(wstage[kr][lcB], wstage[kr + 1][lcB]);
            }
        }
        __syncthreads();
    }

    // barriers + zeroed ht visible cluster-wide before anyone scatters
    asm volatile("barrier.cluster.arrive.aligned;" ::: "memory");
    asm volatile("barrier.cluster.wait.aligned;" ::: "memory");

    // ---- 64 recurrence steps, one __syncthreads each, no cluster barrier ----
    for (int t = 0; t < 64; ++t) {
        if (t > 0) {
            uint32_t ba = mbarb + (uint32_t)((t & 1) * 8);
            mbar_wait(ba, ((t - 1) >> 1) & 1);
            if (tid == 0) mbar_arrive_expect(ba, 2048);   // re-arm for t+2
        }

        // matvec: both batches, gate cols A/B
        float pA[2], pB[2];
        const uint32_t abase = htb + (uint32_t)((t & 1) * 2048 + kq * 128);
#pragma unroll
        for (int b2 = 0; b2 < 2; ++b2) {
            unsigned long long accA = 0ull, accB = 0ull;
            const uint32_t a = abase + (uint32_t)(b2 * 1024);
#pragma unroll
            for (int q = 0; q < 8; ++q) {
                unsigned long long hA, hB;
                asm volatile("ld.shared.v2.u64 {%0, %1}, [%2];"
                             : "=l"(hA), "=l"(hB) : "r"(a + (uint32_t)(q * 16)));
                ffma2(accA, wA[2 * q],     hA);
                ffma2(accA, wA[2 * q + 1], hB);
                ffma2(accB, wB[2 * q],     hA);
                ffma2(accB, wB[2 * q + 1], hB);
            }
            float2 fA = upk2(accA), fB = upk2(accB);
            pA[b2] = fA.x + fA.y;
            pB[b2] = fB.x + fB.y;
        }
        // k-reduce over the 8 kq lanes (intra-warp)
#pragma unroll
        for (int off = 1; off < 8; off <<= 1) {
            pA[0] += __shfl_xor_sync(0xffffffffu, pA[0], off);
            pB[0] += __shfl_xor_sync(0xffffffffu, pB[0], off);
            pA[1] += __shfl_xor_sync(0xffffffffu, pA[1], off);
            pB[1] += __shfl_xor_sync(0xffffffffu, pB[1], off);
        }
        if (kq == 0) {
            gsm[0][2 * cp][hl]     = pA[0];
            gsm[0][2 * cp + 1][hl] = pB[0];
            gsm[1][2 * cp][hl]     = pA[1];
            gsm[1][2 * cp + 1][hl] = pB[1];
        }
        __syncthreads();

        // pointwise + scatter: warps 0,1 (one lane per (b2, h))
        if (tid < 64) {
            int b2 = tid >> 5, l = tid & 31;
            float gi = gsm[b2][0][l] + gb0;
            float gf = gsm[b2][1][l] + gb1;
            float gg = gsm[b2][2][l] + gb2;
            float go = gsm[b2][3][l] + gb3;
            float c  = sigf(gf) * ct + sigf(gi) * tanh_fast(gg);
            ct = c;
            float h  = sigf(go) * tanh_fast(c);

            uint32_t bb    = (uint32_t)((t + 1) & 1);
            uint32_t laddr = htb + (bb * 512u + (uint32_t)(b2 * 256 + r * 32 + l)) * 4u;
            uint32_t lbar  = mbarb + bb * 8u;
#pragma unroll
            for (int rr = 0; rr < 8; ++rr)
                st_async_f32(laddr, lbar, h, rr);
        }
    }

    // final wait: bar0, phase 31 (parity 1) — full ht(step 64 buffer 0) visible
    mbar_wait(mbarb, 1);

    // ---- epilogue: out[b] = ht @ Wf + bf (rank 0 only) ----
    if (r == 0) {
        int b2 = tid >> 8, k = tid & 255;
        float v = htbuf[0][b2][k] * Wf[k];
#pragma unroll
        for (int off = 16; off > 0; off >>= 1) v += __shfl_xor_sync(0xffffffffu, v, off);
        if ((tid & 31) == 0) red_s[tid >> 5] = v;
        __syncthreads();
        if (tid == 0) {
            float o = bf[0];
#pragma unroll
            for (int w = 0; w < 8; ++w) o += red_s[w];
            out[cbase] = o;
        }
        if (tid == 256) {
            float o = bf[0];
#pragma unroll
            for (int w = 8; w < 16; ++w) o += red_s[w];
            out[cbase + 1] = o;
        }
    }
}

// ============================================================================
extern "C" void kernel_launch(void* const* d_in, const int* in_sizes, int n_in,
                              void* d_out, int out_size) {
    (void)in_sizes; (void)n_in; (void)out_size;
    const float* x    = (const float*)d_in[0];
    const float* Wa   = (const float*)d_in[1];
    // d_in[2] = ba : constant across seq, cancels inside softmax — unused
    const float* Wi   = (const float*)d_in[3];
    const float* Wh   = (const float*)d_in[4];
    const float* bias = (const float*)d_in[5];
    const float* Wf   = (const float*)d_in[6];
    const float* bf   = (const float*)d_in[7];
    float* out = (float*)d_out;

    k_context<<<128, 256>>>(x, Wa);
    k_recur<<<128, 512>>>(Wi, Wh, bias, Wf, bf, out);
}